// round 7
// baseline (speedup 1.0000x reference)
#include <cuda_runtime.h>
#include <cuda_bf16.h>
#include <cuda_fp16.h>
#include <cstdint>

#define N_NODES 100000
#define N_EDGES 1600000
#define IN_C    128
#define HID_C   128
#define OUT_C   64
#define N_PAD   100352          // 98*1024 >= N_NODES+1
#define NBLK    98              // scan chunks of 1024

// Scratch (no allocations allowed -> __device__ globals)
__device__ __half g_hs1h[(size_t)N_NODES * HID_C]; // fp16 inv[s]*h1[s]
__device__ __half g_hs2h[(size_t)N_NODES * OUT_C]; // fp16 inv[s]*h2[s]
__device__ int    g_deg [N_NODES];
__device__ float  g_inv [N_NODES];
__device__ int    g_ro  [N_PAD];
__device__ int    g_cur [N_PAD];
__device__ int    g_csr [N_EDGES];
__device__ int    g_bsum[128];

// ---------------------------------------------------------------------------
// helpers
// ---------------------------------------------------------------------------
__device__ __forceinline__ uint32_t smem_u32(const void* p) {
    uint32_t a;
    asm("{ .reg .u64 t; cvta.to.shared.u64 t, %1; cvt.u32.u64 %0, t; }" : "=r"(a) : "l"(p));
    return a;
}
__device__ __forceinline__ void ldm_x4(uint32_t* r, uint32_t addr) {
    asm volatile("ldmatrix.sync.aligned.m8n8.x4.shared.b16 {%0,%1,%2,%3}, [%4];"
                 : "=r"(r[0]), "=r"(r[1]), "=r"(r[2]), "=r"(r[3]) : "r"(addr));
}
__device__ __forceinline__ void ldm_x4t(uint32_t* r, uint32_t addr) {
    asm volatile("ldmatrix.sync.aligned.m8n8.x4.trans.shared.b16 {%0,%1,%2,%3}, [%4];"
                 : "=r"(r[0]), "=r"(r[1]), "=r"(r[2]), "=r"(r[3]) : "r"(addr));
}
__device__ __forceinline__ void mma_bf16(float* c, const uint32_t* a, const uint32_t* b) {
    asm volatile("mma.sync.aligned.m16n8k16.row.col.f32.bf16.bf16.f32 "
                 "{%0,%1,%2,%3}, {%4,%5,%6,%7}, {%8,%9}, {%0,%1,%2,%3};"
                 : "+f"(c[0]), "+f"(c[1]), "+f"(c[2]), "+f"(c[3])
                 : "r"(a[0]), "r"(a[1]), "r"(a[2]), "r"(a[3]), "r"(b[0]), "r"(b[1]));
}
__device__ __forceinline__ uint32_t pack_bf16(float a, float b, float& ra, float& rb) {
    __nv_bfloat16 ha = __float2bfloat16(a), hb = __float2bfloat16(b);
    ra = a - __bfloat162float(ha);
    rb = b - __bfloat162float(hb);
    return (uint32_t)__bfloat16_as_ushort(ha) | ((uint32_t)__bfloat16_as_ushort(hb) << 16);
}
__device__ __forceinline__ uint32_t pack_bf16_lo(float a, float b) {
    return (uint32_t)__bfloat16_as_ushort(__float2bfloat16(a))
         | ((uint32_t)__bfloat16_as_ushort(__float2bfloat16(b)) << 16);
}
// Per-block edge dtype sniff (int64 vs int32 layout).
__device__ __forceinline__ int block_is32(const void* ei) {
    const long long* p = (const long long*)ei;
    int lane = threadIdx.x & 31;
    int bad = 0;
    if (threadIdx.x < 32) {
        long long v = p[lane];
        bad = (v < 0 || v >= N_NODES) ? 1 : 0;
    }
    __shared__ int sh_is32;
    if (threadIdx.x < 32) {
        unsigned m = __ballot_sync(0xFFFFFFFFu, bad);
        if (lane == 0) sh_is32 = (m != 0);
    }
    __syncthreads();
    return sh_is32;
}
__device__ __forceinline__ int edge_val(const void* ei, int is32, long long idx) {
    if (is32) return ((const int*)ei)[idx];
    return (int)(((const long long*)ei)[idx]);
}

// ---------------------------------------------------------------------------
// setup
// ---------------------------------------------------------------------------
__global__ void k_count(const void* __restrict__ ei) {
    int is32 = block_is32(ei);
    int e = blockIdx.x * blockDim.x + threadIdx.x;
    if (e < N_EDGES) {
        int d = edge_val(ei, is32, (long long)N_EDGES + e);
        atomicAdd(&g_deg[d], 1);
    }
}
// per-1024-chunk sums + g_inv
__global__ __launch_bounds__(1024) void k_sum() {
    __shared__ int sh[32];
    int t = threadIdx.x;
    int i = blockIdx.x * 1024 + t;
    int v = (i < N_NODES) ? g_deg[i] : 0;
    if (i < N_NODES) g_inv[i] = rsqrtf((float)(v + 1));
    int w = v;
    #pragma unroll
    for (int o = 16; o; o >>= 1) w += __shfl_down_sync(0xFFFFFFFFu, w, o);
    if ((t & 31) == 0) sh[t >> 5] = w;
    __syncthreads();
    if (t < 32) {
        int x = sh[t];
        #pragma unroll
        for (int o = 16; o; o >>= 1) x += __shfl_down_sync(0xFFFFFFFFu, x, o);
        if (t == 0) g_bsum[blockIdx.x] = x;
    }
}
// full exclusive scan: every block sums its predecessors' chunk sums, then
// scans its own 1024-chunk; writes g_ro and g_cur.
__global__ __launch_bounds__(1024) void k_scan() {
    __shared__ int soff;
    __shared__ int wsum[32];
    __shared__ int bs[128];
    int t = threadIdx.x;
    if (t < 128) bs[t] = (t < NBLK) ? g_bsum[t] : 0;
    __syncthreads();
    if (t == 0) {
        int s = 0;
        for (int b = 0; b < blockIdx.x; b++) s += bs[b];
        soff = s;
    }
    int i = blockIdx.x * 1024 + t;
    int v = (i < N_NODES) ? g_deg[i] : 0;
    int x = v;
    #pragma unroll
    for (int o = 1; o < 32; o <<= 1) {
        int y = __shfl_up_sync(0xFFFFFFFFu, x, o);
        if ((t & 31) >= o) x += y;
    }
    if ((t & 31) == 31) wsum[t >> 5] = x;
    __syncthreads();
    if (t < 32) {
        int y = wsum[t], z = y;
        #pragma unroll
        for (int o = 1; o < 32; o <<= 1) {
            int q = __shfl_up_sync(0xFFFFFFFFu, z, o);
            if (t >= o) z += q;
        }
        wsum[t] = z - y;   // exclusive
    }
    __syncthreads();
    int excl = soff + wsum[t >> 5] + x - v;
    g_ro[i]  = excl;
    g_cur[i] = excl;
}
__global__ void k_fill(const void* __restrict__ ei) {
    int is32 = block_is32(ei);
    int e = blockIdx.x * blockDim.x + threadIdx.x;
    if (e < N_EDGES) {
        int s = edge_val(ei, is32, e);
        int d = edge_val(ei, is32, (long long)N_EDGES + e);
        int pos = atomicAdd(&g_cur[d], 1);
        g_csr[pos] = s;
    }
}

// ---------------------------------------------------------------------------
// GEMM1 (warp-MMA split-bf16): hs1 = fp16( inv[row] * (X @ W1) ), NC=128
// ---------------------------------------------------------------------------
__global__ __launch_bounds__(256, 1) void k_gemm1(const float* __restrict__ A,
                                                  const float* __restrict__ W,
                                                  __half* __restrict__ Out) {
    constexpr int NC = 128, WN = 64, NT = 8, AST = 136, BST = 136;
    constexpr int A_HI = 0;
    constexpr int A_LO = 128 * AST * 2;
    constexpr int B_HI = 2 * 128 * AST * 2;
    constexpr int B_LO = B_HI + 128 * BST * 2;

    extern __shared__ char smem[];
    const uint32_t sb = smem_u32(smem);
    const int tid = threadIdx.x, wid = tid >> 5, lane = tid & 31;
    const int blockRow = blockIdx.x * 128;

    for (int idx = tid; idx < 128 * 64; idx += 256) {
        int r = idx >> 6, k2 = (idx & 63) << 1;
        int row = blockRow + r;
        float a0 = 0.f, a1 = 0.f;
        if (row < N_NODES) {
            float2 v = *(const float2*)(A + (size_t)row * 128 + k2);
            a0 = v.x; a1 = v.y;
        }
        float l0, l1;
        uint32_t hi = pack_bf16(a0, a1, l0, l1);
        uint32_t lo = pack_bf16_lo(l0, l1);
        uint32_t off = (uint32_t)(r * AST + k2) * 2;
        *(uint32_t*)(smem + A_HI + off) = hi;
        *(uint32_t*)(smem + A_LO + off) = lo;
    }
    for (int idx = tid; idx < 128 * 64; idx += 256) {
        int k = idx >> 6, n2 = (idx & 63) << 1;
        float2 w = *(const float2*)(W + (size_t)k * NC + n2);
        float l0, l1;
        uint32_t hi = pack_bf16(w.x, w.y, l0, l1);
        uint32_t lo = pack_bf16_lo(l0, l1);
        uint32_t off = (uint32_t)(k * BST + n2) * 2;
        *(uint32_t*)(smem + B_HI + off) = hi;
        *(uint32_t*)(smem + B_LO + off) = lo;
    }
    __syncthreads();

    const int wm = (wid & 3) * 32;
    const int wn = (wid >> 2) * WN;
    float acc[2][NT][4];
    #pragma unroll
    for (int mt = 0; mt < 2; mt++)
        #pragma unroll
        for (int nt = 0; nt < NT; nt++)
            #pragma unroll
            for (int i = 0; i < 4; i++) acc[mt][nt][i] = 0.f;

    const int laA = lane & 15, lbA = lane >> 4;
    const int rB = (((lane >> 3) & 1) << 3) + (lane & 7);
    const int cB = (lane >> 4) << 3;

    #pragma unroll
    for (int ks = 0; ks < 8; ks++) {
        const int k0 = ks * 16;
        uint32_t a_hi[2][4], a_lo[2][4], bh[NT][2], bl[NT][2];
        #pragma unroll
        for (int mt = 0; mt < 2; mt++) {
            uint32_t addr = sb + A_HI + (uint32_t)((wm + mt * 16 + laA) * AST + k0 + lbA * 8) * 2;
            ldm_x4(a_hi[mt], addr);
            ldm_x4(a_lo[mt], addr + (A_LO - A_HI));
        }
        #pragma unroll
        for (int nt2 = 0; nt2 < NT / 2; nt2++) {
            uint32_t addr = sb + B_HI + (uint32_t)((k0 + rB) * BST + wn + nt2 * 16 + cB) * 2;
            uint32_t t[4];
            ldm_x4t(t, addr);
            bh[2 * nt2][0] = t[0]; bh[2 * nt2][1] = t[1];
            bh[2 * nt2 + 1][0] = t[2]; bh[2 * nt2 + 1][1] = t[3];
            ldm_x4t(t, addr + (B_LO - B_HI));
            bl[2 * nt2][0] = t[0]; bl[2 * nt2][1] = t[1];
            bl[2 * nt2 + 1][0] = t[2]; bl[2 * nt2 + 1][1] = t[3];
        }
        #pragma unroll
        for (int mt = 0; mt < 2; mt++)
            #pragma unroll
            for (int nt = 0; nt < NT; nt++) {
                mma_bf16(acc[mt][nt], a_hi[mt], bh[nt]);
                mma_bf16(acc[mt][nt], a_hi[mt], bl[nt]);
                mma_bf16(acc[mt][nt], a_lo[mt], bh[nt]);
            }
    }

    #pragma unroll
    for (int mt = 0; mt < 2; mt++) {
        int row0 = blockRow + wm + mt * 16 + (lane >> 2);
        int row1 = row0 + 8;
        float iv0 = (row0 < N_NODES) ? g_inv[row0] : 0.f;
        float iv1 = (row1 < N_NODES) ? g_inv[row1] : 0.f;
        #pragma unroll
        for (int nt = 0; nt < NT; nt++) {
            int col = wn + nt * 8 + (lane & 3) * 2;
            if (row0 < N_NODES) {
                __half2 h = __floats2half2_rn(iv0 * acc[mt][nt][0], iv0 * acc[mt][nt][1]);
                *(__half2*)(Out + (size_t)row0 * NC + col) = h;
            }
            if (row1 < N_NODES) {
                __half2 h = __floats2half2_rn(iv1 * acc[mt][nt][2], iv1 * acc[mt][nt][3]);
                *(__half2*)(Out + (size_t)row1 * NC + col) = h;
            }
        }
    }
}

// ---------------------------------------------------------------------------
// FUSED agg1 + GEMM2: block = 128 dst nodes.
//  Phase A: a1[r] = relu(inv*(hs1[r] + sum_src hs1[src]) + b1) -> bf16 hi/lo smem
//  Phase B: hs2[r] = fp16( inv[r] * (a1 @ W2) )     (NC = 64)
// ---------------------------------------------------------------------------
__global__ __launch_bounds__(256, 1) void k_fuse(const float* __restrict__ W2,
                                                 const float* __restrict__ b1,
                                                 __half* __restrict__ Out) {
    constexpr int NC = 64, WN = 32, NT = 4, AST = 136, BST = 72;
    constexpr int A_HI = 0;
    constexpr int A_LO = 128 * AST * 2;
    constexpr int B_HI = 2 * 128 * AST * 2;
    constexpr int B_LO = B_HI + 128 * BST * 2;

    extern __shared__ char smem[];
    const uint32_t sb = smem_u32(smem);
    const int tid = threadIdx.x, wid = tid >> 5, lane = tid & 31;
    const int blockRow = blockIdx.x * 128;

    // ---- B fill from W2 [128][64] ----
    for (int idx = tid; idx < 128 * 32; idx += 256) {
        int k = idx >> 5, n2 = (idx & 31) << 1;
        float2 w = *(const float2*)(W2 + (size_t)k * NC + n2);
        float l0, l1;
        uint32_t hi = pack_bf16(w.x, w.y, l0, l1);
        uint32_t lo = pack_bf16_lo(l0, l1);
        uint32_t off = (uint32_t)(k * BST + n2) * 2;
        *(uint32_t*)(smem + B_HI + off) = hi;
        *(uint32_t*)(smem + B_LO + off) = lo;
    }

    // ---- Phase A: aggregate into A tiles (half-warp = 1 node, 8 passes) ----
    {
        const int hw = tid >> 4, l = tid & 15;   // 16 half-warps x 16 lanes(8 ch)
        const uint4* base = (const uint4*)g_hs1h;
        float4 bb0 = __ldg((const float4*)b1 + l * 2);
        float4 bb1 = __ldg((const float4*)b1 + l * 2 + 1);
        #pragma unroll 1
        for (int pass = 0; pass < 8; pass++) {
            int r = pass * 16 + hw;
            int node = blockRow + r;
            float a[8] = {0.f, 0.f, 0.f, 0.f, 0.f, 0.f, 0.f, 0.f};
            if (node < N_NODES) {
                uint4 sv = __ldg(&base[(size_t)node * 16 + l]);
                float2 p0 = __half22float2(*(__half2*)&sv.x);
                float2 p1 = __half22float2(*(__half2*)&sv.y);
                float2 p2 = __half22float2(*(__half2*)&sv.z);
                float2 p3 = __half22float2(*(__half2*)&sv.w);
                a[0]=p0.x; a[1]=p0.y; a[2]=p1.x; a[3]=p1.y;
                a[4]=p2.x; a[5]=p2.y; a[6]=p3.x; a[7]=p3.y;
                int j  = g_ro[node];
                int je = g_ro[node + 1];
                for (; j + 3 < je; j += 4) {
                    int s0 = __ldg(&g_csr[j]),     s1 = __ldg(&g_csr[j + 1]);
                    int s2 = __ldg(&g_csr[j + 2]), s3 = __ldg(&g_csr[j + 3]);
                    uint4 v0 = __ldg(&base[(size_t)s0 * 16 + l]);
                    uint4 v1 = __ldg(&base[(size_t)s1 * 16 + l]);
                    uint4 v2 = __ldg(&base[(size_t)s2 * 16 + l]);
                    uint4 v3 = __ldg(&base[(size_t)s3 * 16 + l]);
                    #pragma unroll
                    for (int q = 0; q < 4; q++) {
                        uint4 v = (q == 0) ? v0 : (q == 1) ? v1 : (q == 2) ? v2 : v3;
                        float2 p0q = __half22float2(*(__half2*)&v.x);
                        float2 p1q = __half22float2(*(__half2*)&v.y);
                        float2 p2q = __half22float2(*(__half2*)&v.z);
                        float2 p3q = __half22float2(*(__half2*)&v.w);
                        a[0]+=p0q.x; a[1]+=p0q.y; a[2]+=p1q.x; a[3]+=p1q.y;
                        a[4]+=p2q.x; a[5]+=p2q.y; a[6]+=p3q.x; a[7]+=p3q.y;
                    }
                }
                for (; j < je; j++) {
                    int s0 = __ldg(&g_csr[j]);
                    uint4 v = __ldg(&base[(size_t)s0 * 16 + l]);
                    float2 p0q = __half22float2(*(__half2*)&v.x);
                    float2 p1q = __half22float2(*(__half2*)&v.y);
                    float2 p2q = __half22float2(*(__half2*)&v.z);
                    float2 p3q = __half22float2(*(__half2*)&v.w);
                    a[0]+=p0q.x; a[1]+=p0q.y; a[2]+=p1q.x; a[3]+=p1q.y;
                    a[4]+=p2q.x; a[5]+=p2q.y; a[6]+=p3q.x; a[7]+=p3q.y;
                }
                float iv = g_inv[node];
                a[0]=fmaxf(iv*a[0]+bb0.x,0.f); a[1]=fmaxf(iv*a[1]+bb0.y,0.f);
                a[2]=fmaxf(iv*a[2]+bb0.z,0.f); a[3]=fmaxf(iv*a[3]+bb0.w,0.f);
                a[4]=fmaxf(iv*a[4]+bb1.x,0.f); a[5]=fmaxf(iv*a[5]+bb1.y,0.f);
                a[6]=fmaxf(iv*a[6]+bb1.z,0.f); a[7]=fmaxf(iv*a[7]+bb1.w,0.f);
            }
            // split fp32 -> bf16 hi/lo, write A tiles (k = l*8 + i)
            uint32_t off = (uint32_t)(r * AST + l * 8) * 2;
            #pragma unroll
            for (int i = 0; i < 4; i++) {
                float l0, l1;
                uint32_t hi = pack_bf16(a[2 * i], a[2 * i + 1], l0, l1);
                uint32_t lo = pack_bf16_lo(l0, l1);
                *(uint32_t*)(smem + A_HI + off + i * 4) = hi;
                *(uint32_t*)(smem + A_LO + off + i * 4) = lo;
            }
        }
    }
    __syncthreads();

    // ---- Phase B: MMA ----
    const int wm = (wid & 3) * 32;
    const int wn = (wid >> 2) * WN;
    float acc[2][NT][4];
    #pragma unroll
    for (int mt = 0; mt < 2; mt++)
        #pragma unroll
        for (int nt = 0; nt < NT; nt++)
            #pragma unroll
            for (int i = 0; i < 4; i++) acc[mt][nt][i] = 0.f;

    const int laA = lane & 15, lbA = lane >> 4;
    const int rB = (((lane >> 3) & 1) << 3) + (lane & 7);
    const int cB = (lane >> 4) << 3;

    #pragma unroll
    for (int ks = 0; ks < 8; ks++) {
        const int k0 = ks * 16;
        uint32_t a_hi[2][4], a_lo[2][4], bh[NT][2], bl[NT][2];
        #pragma unroll
        for (int mt = 0; mt < 2; mt++) {
            uint32_t addr = sb + A_HI + (uint32_t)((wm + mt * 16 + laA) * AST + k0 + lbA * 8) * 2;
            ldm_x4(a_hi[mt], addr);
            ldm_x4(a_lo[mt], addr + (A_LO - A_HI));
        }
        #pragma unroll
        for (int nt2 = 0; nt2 < NT / 2; nt2++) {
            uint32_t addr = sb + B_HI + (uint32_t)((k0 + rB) * BST + wn + nt2 * 16 + cB) * 2;
            uint32_t t[4];
            ldm_x4t(t, addr);
            bh[2 * nt2][0] = t[0]; bh[2 * nt2][1] = t[1];
            bh[2 * nt2 + 1][0] = t[2]; bh[2 * nt2 + 1][1] = t[3];
            ldm_x4t(t, addr + (B_LO - B_HI));
            bl[2 * nt2][0] = t[0]; bl[2 * nt2][1] = t[1];
            bl[2 * nt2 + 1][0] = t[2]; bl[2 * nt2 + 1][1] = t[3];
        }
        #pragma unroll
        for (int mt = 0; mt < 2; mt++)
            #pragma unroll
            for (int nt = 0; nt < NT; nt++) {
                mma_bf16(acc[mt][nt], a_hi[mt], bh[nt]);
                mma_bf16(acc[mt][nt], a_hi[mt], bl[nt]);
                mma_bf16(acc[mt][nt], a_lo[mt], bh[nt]);
            }
    }

    // ---- epilogue: hs2 = fp16(inv*acc) ----
    #pragma unroll
    for (int mt = 0; mt < 2; mt++) {
        int row0 = blockRow + wm + mt * 16 + (lane >> 2);
        int row1 = row0 + 8;
        float iv0 = (row0 < N_NODES) ? g_inv[row0] : 0.f;
        float iv1 = (row1 < N_NODES) ? g_inv[row1] : 0.f;
        #pragma unroll
        for (int nt = 0; nt < NT; nt++) {
            int col = wn + nt * 8 + (lane & 3) * 2;
            if (row0 < N_NODES) {
                __half2 h = __floats2half2_rn(iv0 * acc[mt][nt][0], iv0 * acc[mt][nt][1]);
                *(__half2*)(Out + (size_t)row0 * NC + col) = h;
            }
            if (row1 < N_NODES) {
                __half2 h = __floats2half2_rn(iv1 * acc[mt][nt][2], iv1 * acc[mt][nt][3]);
                *(__half2*)(Out + (size_t)row1 * NC + col) = h;
            }
        }
    }
}

// ---------------------------------------------------------------------------
// agg2: eighth-warp (8 lanes x uint4) per node, unroll-4, fp32 accum.
// out[d] = inv[d]*(hs2[d] + sum_src hs2[src]) + b2     (out fp32)
// ---------------------------------------------------------------------------
__global__ __launch_bounds__(256) void k_agg2(float* __restrict__ out,
                                              const float* __restrict__ b2) {
    int node = blockIdx.x * 32 + (threadIdx.x >> 3);
    if (node >= N_NODES) return;
    int l = threadIdx.x & 7;
    const uint4* base = (const uint4*)g_hs2h;

    float a[8];
    {
        uint4 sv = __ldg(&base[(size_t)node * 8 + l]);
        float2 p0 = __half22float2(*(__half2*)&sv.x);
        float2 p1 = __half22float2(*(__half2*)&sv.y);
        float2 p2 = __half22float2(*(__half2*)&sv.z);
        float2 p3 = __half22float2(*(__half2*)&sv.w);
        a[0]=p0.x; a[1]=p0.y; a[2]=p1.x; a[3]=p1.y; a[4]=p2.x; a[5]=p2.y; a[6]=p3.x; a[7]=p3.y;
    }
    int j  = g_ro[node];
    int je = g_ro[node + 1];
    for (; j + 3 < je; j += 4) {
        int s0 = __ldg(&g_csr[j]),     s1 = __ldg(&g_csr[j + 1]);
        int s2 = __ldg(&g_csr[j + 2]), s3 = __ldg(&g_csr[j + 3]);
        uint4 v0 = __ldg(&base[(size_t)s0 * 8 + l]);
        uint4 v1 = __ldg(&base[(size_t)s1 * 8 + l]);
        uint4 v2 = __ldg(&base[(size_t)s2 * 8 + l]);
        uint4 v3 = __ldg(&base[(size_t)s3 * 8 + l]);
        #pragma unroll
        for (int q = 0; q < 4; q++) {
            uint4 v = (q == 0) ? v0 : (q == 1) ? v1 : (q == 2) ? v2 : v3;
            float2 p0 = __half22float2(*(__half2*)&v.x);
            float2 p1 = __half22float2(*(__half2*)&v.y);
            float2 p2 = __half22float2(*(__half2*)&v.z);
            float2 p3 = __half22float2(*(__half2*)&v.w);
            a[0]+=p0.x; a[1]+=p0.y; a[2]+=p1.x; a[3]+=p1.y;
            a[4]+=p2.x; a[5]+=p2.y; a[6]+=p3.x; a[7]+=p3.y;
        }
    }
    for (; j < je; j++) {
        int s0 = __ldg(&g_csr[j]);
        uint4 v = __ldg(&base[(size_t)s0 * 8 + l]);
        float2 p0 = __half22float2(*(__half2*)&v.x);
        float2 p1 = __half22float2(*(__half2*)&v.y);
        float2 p2 = __half22float2(*(__half2*)&v.z);
        float2 p3 = __half22float2(*(__half2*)&v.w);
        a[0]+=p0.x; a[1]+=p0.y; a[2]+=p1.x; a[3]+=p1.y;
        a[4]+=p2.x; a[5]+=p2.y; a[6]+=p3.x; a[7]+=p3.y;
    }
    float iv = g_inv[node];
    float4 bb0 = __ldg((const float4*)b2 + l * 2);
    float4 bb1 = __ldg((const float4*)b2 + l * 2 + 1);
    float4 o0, o1;
    o0.x = iv*a[0]+bb0.x; o0.y = iv*a[1]+bb0.y; o0.z = iv*a[2]+bb0.z; o0.w = iv*a[3]+bb0.w;
    o1.x = iv*a[4]+bb1.x; o1.y = iv*a[5]+bb1.y; o1.z = iv*a[6]+bb1.z; o1.w = iv*a[7]+bb1.w;
    float4* ob = (float4*)(out + (size_t)node * OUT_C + l * 8);
    ob[0] = o0; ob[1] = o1;
}

// ---------------------------------------------------------------------------
extern "C" void kernel_launch(void* const* d_in, const int* in_sizes, int n_in,
                              void* d_out, int out_size) {
    const float* x  = (const float*)d_in[0];
    const void*  ei = d_in[1];
    const float* W1 = (const float*)d_in[2];
    const float* b1 = (const float*)d_in[3];
    const float* W2 = (const float*)d_in[4];
    const float* b2 = (const float*)d_in[5];
    float* out = (float*)d_out;

    const int SMEM1 = 2 * 128 * 136 * 2 + 2 * 128 * 136 * 2;  // 139264
    const int SMEM2 = 2 * 128 * 136 * 2 + 2 * 128 * 72 * 2;   // 106496

    cudaFuncSetAttribute(k_gemm1, cudaFuncAttributeMaxDynamicSharedMemorySize, SMEM1);
    cudaFuncSetAttribute(k_fuse,  cudaFuncAttributeMaxDynamicSharedMemorySize, SMEM2);

    __half* hs1 = nullptr; cudaGetSymbolAddress((void**)&hs1, g_hs1h);
    __half* hs2 = nullptr; cudaGetSymbolAddress((void**)&hs2, g_hs2h);
    int* degp   = nullptr; cudaGetSymbolAddress((void**)&degp, g_deg);

    cudaMemsetAsync(degp, 0, N_NODES * sizeof(int));
    k_count <<<(N_EDGES + 255) / 256, 256>>>(ei);
    k_sum   <<<NBLK, 1024>>>();
    k_scan  <<<NBLK, 1024>>>();
    k_fill  <<<(N_EDGES + 255) / 256, 256>>>(ei);

    k_gemm1 <<<(N_NODES + 127) / 128, 256, SMEM1>>>(x, W1, hs1);
    k_fuse  <<<(N_NODES + 127) / 128, 256, SMEM2>>>(W2, b1, hs2);
    k_agg2  <<<(N_NODES + 31) / 32, 256>>>(out, b2);
}